// round 15
// baseline (speedup 1.0000x reference)
#include <cuda_runtime.h>
#include <cuda_bf16.h>
#include <cstdint>

#define I_DIM 1024
#define J_DIM 50000
#define J_PAD 50048            // 391 * 128
#define D_DIM 512
#define NCLS  10
#define BI 128
#define BJ 128
#define NCHUNK 8               // K chunks of 64 bf16 (128B per row)
#define STAGES 3
#define NTHREADS 128
#define NTILES ((I_DIM / BI) * (J_PAD / BJ))   // 3128
#define NCTAS 304                              // 2/SM x 152 (GB300 die)
#define TFULL (NCTAS * 10)                     // 3040 tiles done as full tiles (10/CTA)
#define NREM  (NTILES - TFULL)                 // 88 remainder tiles, K-split across CTA pairs

// ---- dynamic smem layout (bytes) ----
#define STAGE_BYTES 32768      // A 16KB + B 16KB
#define SM_LABS   (STAGES * STAGE_BYTES)        // 98304: 2 x 128 ints (double-buffered)
#define SM_ESQ    (SM_LABS + 1024)              // 2 x 128 floats
#define SM_LOGIT  (SM_ESQ + 1024)               // 128*10 floats
#define SM_TOTAL  (SM_LOGIT + 5120)             // 105472 (x2 CTAs <= 227KB)

// ---------------- device scratch ----------------
__device__ __align__(16) __nv_bfloat16 g_xb[I_DIM * D_DIM];   // x * Sigma_inv
__device__ __align__(16) __nv_bfloat16 g_eb[J_PAD * D_DIM];   // exemplars
__device__ float g_xsq[I_DIM];
__device__ float g_esq[J_PAD];
__device__ float g_logits[I_DIM * NCLS];   // zero at load; re-zeroed by softmax_k each call
__device__ float g_part[NREM * BI * BJ];   // K-split partial accumulators (rewritten identically each launch)
__device__ int   g_pflag[NREM];            // stale-safe flags (identical rewrites)

// ---------------- helpers ----------------
__device__ __forceinline__ uint32_t smem_u32(const void* p) {
    uint32_t a;
    asm("{ .reg .u64 t; cvta.to.shared.u64 t, %1; cvt.u32.u64 %0, t; }" : "=r"(a) : "l"(p));
    return a;
}
__device__ __forceinline__ void cp16(uint32_t dst, const void* src) {
    asm volatile("cp.async.cg.shared.global [%0], [%1], 16;" :: "r"(dst), "l"(src));
}
__device__ __forceinline__ void cp_commit() {
    asm volatile("cp.async.commit_group;" ::: "memory");
}
template <int N>
__device__ __forceinline__ void cp_wait() {
    asm volatile("cp.async.wait_group %0;" :: "n"(N) : "memory");
}
__device__ __forceinline__ void ldsm_x4(uint32_t r[4], uint32_t addr) {
    asm volatile("ldmatrix.sync.aligned.m8n8.x4.shared.b16 {%0,%1,%2,%3}, [%4];"
                 : "=r"(r[0]), "=r"(r[1]), "=r"(r[2]), "=r"(r[3]) : "r"(addr));
}
__device__ __forceinline__ void mma_bf16(float c[4], const uint32_t a[4], uint32_t b0, uint32_t b1) {
    asm volatile(
        "mma.sync.aligned.m16n8k16.row.col.f32.bf16.bf16.f32 "
        "{%0,%1,%2,%3}, {%4,%5,%6,%7}, {%8,%9}, {%0,%1,%2,%3};\n"
        : "+f"(c[0]), "+f"(c[1]), "+f"(c[2]), "+f"(c[3])
        : "r"(a[0]), "r"(a[1]), "r"(a[2]), "r"(a[3]), "r"(b0), "r"(b1));
}
__device__ __forceinline__ uint32_t pack_bf16(float lo, float hi) {
    uint32_t r;
    asm("cvt.rn.satfinite.bf16x2.f32 %0, %1, %2;" : "=r"(r) : "f"(hi), "f"(lo));
    return r;
}
// packed bf16x2 one-hot: {a==c, b==c}
__device__ __forceinline__ uint32_t onehot2(int a, int b, int c) {
    return ((a == c) ? 0x3F80u : 0u) | (((b == c) ? 0x3F80u : 0u) << 16);
}

// ---------------- prep: x & E convert + row norms (one kernel) ----------------
__global__ void prep_all(const float4* __restrict__ x4, const float4* __restrict__ e4,
                         const float4* __restrict__ S4) {
    const int blk  = blockIdx.x;
    const int wid  = threadIdx.x >> 5;
    const int lane = threadIdx.x & 31;

    // ---- E part (all blocks) ----
    {
        int row = blk * 8 + wid;
        uint2* dst = ((uint2*)g_eb) + (size_t)row * 128;
        if (row >= J_DIM) {
            uint2 z = {0u, 0u};
#pragma unroll
            for (int i = 0; i < 4; i++) dst[i * 32 + lane] = z;
            if (lane == 0) g_esq[row] = 0.f;
        } else {
            float sq = 0.f;
#pragma unroll
            for (int i = 0; i < 4; i++) {
                int idx = i * 32 + lane;
                float4 v = e4[(size_t)row * 128 + idx];
                float4 s = S4[idx];
                sq += v.x * v.x * s.x + v.y * v.y * s.y + v.z * v.z * s.z + v.w * v.w * s.w;
                uint2 o; o.x = pack_bf16(v.x, v.y); o.y = pack_bf16(v.z, v.w);
                dst[idx] = o;
            }
#pragma unroll
            for (int o = 16; o; o >>= 1) sq += __shfl_xor_sync(0xffffffffu, sq, o);
            if (lane == 0) g_esq[row] = sq;
        }
    }

    // ---- x part (blocks 0..127) ----
    if (blk < I_DIM / 8) {
        int row = blk * 8 + wid;
        float sq = 0.f;
        uint2* dst = ((uint2*)g_xb) + (size_t)row * 128;
#pragma unroll
        for (int i = 0; i < 4; i++) {
            int idx = i * 32 + lane;
            float4 v = x4[(size_t)row * 128 + idx];
            float4 s = S4[idx];
            float a0 = v.x * s.x, a1 = v.y * s.y, a2 = v.z * s.z, a3 = v.w * s.w;
            sq += v.x * a0 + v.y * a1 + v.z * a2 + v.w * a3;
            uint2 o; o.x = pack_bf16(a0, a1); o.y = pack_bf16(a2, a3);
            dst[idx] = o;
        }
#pragma unroll
        for (int o = 16; o; o >>= 1) sq += __shfl_xor_sync(0xffffffffu, sq, o);
        if (lane == 0) g_xsq[row] = sq;
    }
}

// ---------------- persistent fused GEMM + K-split remainder ----------------
__global__ __launch_bounds__(NTHREADS, 2)
void gemm_fused(const int* __restrict__ labels, const float* __restrict__ beta_p) {
    extern __shared__ char smem[];
    const uint32_t sbase = smem_u32(smem);
    const int tid  = threadIdx.x;
    const int warp = tid >> 5;
    const int lane = tid & 31;
    const int gid  = lane >> 2;    // 0..7
    const int tig  = lane & 3;     // 0..3
    const int bid  = blockIdx.x;
    const int wi = warp & 1;       // i-half (64 rows)
    const int wj = warp >> 1;      // j-half (64 cols)

    int*   labs_s  = (int*)(smem + SM_LABS);     // [2][128]
    float* esq_s   = (float*)(smem + SM_ESQ);    // [2][128]
    float* logit_s = (float*)(smem + SM_LOGIT);

#pragma unroll
    for (int i = tid; i < BI * NCLS; i += NTHREADS) logit_s[i] = 0.f;

    // per-lane ldmatrix geometry (loop-invariant)
    const int lr = lane & 7;
    const int aRowOff = lr + ((lane >> 3) & 1) * 8;
    const int aColSel = (lane >> 4) << 4;
    const int bRowOff = lr + (lane >> 4) * 8;
    const int bColSel = ((lane >> 3) & 1) << 4;
    const int swx = lr << 4;

    uint32_t axt[4], bxt[4];
#pragma unroll
    for (int ks = 0; ks < 4; ks++) {
        axt[ks] = (uint32_t)((ks * 32 + aColSel) ^ swx);
        bxt[ks] = (uint32_t)((ks * 32 + bColSel) ^ swx);
    }
    const uint32_t aWarp = (uint32_t)((wi * 64 + aRowOff) * 128);
    const uint32_t bWarp = (uint32_t)((wj * 64 + bRowOff) * 128) + 16384;  // B after A (16KB)

    const float beta = beta_p[0];

    // tile t -> iBase = (t&7)*128, jBase = (t>>3)*128
#define STAGE_LOADS(t, chunk, buf)                                           \
    {                                                                        \
        const char* gA_ = (const char*)g_xb + (size_t)(((t) & 7) * BI) * 1024;   \
        const char* gB_ = (const char*)g_eb + (size_t)(((t) >> 3) * BJ) * 1024;  \
        const uint32_t dA = sbase + (buf) * STAGE_BYTES;                     \
        const uint32_t dB = dA + 16384;                                      \
        _Pragma("unroll")                                                    \
        for (int it = 0; it < 8; it++) {                                     \
            int idx = tid + it * NTHREADS;                                   \
            int r = idx >> 3, q = idx & 7;                                   \
            int off = r * 128 + ((q * 16) ^ ((r & 7) << 4));                 \
            cp16(dA + off, gA_ + (size_t)r * 1024 + (chunk) * 128 + q * 16); \
            cp16(dB + off, gB_ + (size_t)r * 1024 + (chunk) * 128 + q * 16); \
        }                                                                    \
    }

// inner ldsm + mma block for one chunk residing in buffer `bufidx`
#define COMPUTE_CHUNK(bufidx)                                                  \
    {                                                                          \
        const uint32_t aCB = sbase + (bufidx) * STAGE_BYTES + aWarp;           \
        const uint32_t bCB = sbase + (bufidx) * STAGE_BYTES + bWarp;           \
        _Pragma("unroll")                                                      \
        for (int mb = 0; mb < 4; mb++) ldsm_x4(afr[0][mb], aCB + mb * 2048 + axt[0]); \
        _Pragma("unroll")                                                      \
        for (int p = 0; p < 4; p++)  ldsm_x4(bfr[0][p],  bCB + p * 2048 + bxt[0]);    \
        _Pragma("unroll")                                                      \
        for (int ks = 0; ks < 4; ks++) {                                       \
            const int cur = ks & 1;                                            \
            if (ks < 3) {                                                      \
                _Pragma("unroll")                                              \
                for (int mb = 0; mb < 4; mb++)                                 \
                    ldsm_x4(afr[cur ^ 1][mb], aCB + mb * 2048 + axt[ks + 1]);  \
                _Pragma("unroll")                                              \
                for (int p = 0; p < 4; p++)                                    \
                    ldsm_x4(bfr[cur ^ 1][p], bCB + p * 2048 + bxt[ks + 1]);    \
            }                                                                  \
            _Pragma("unroll")                                                  \
            for (int mb = 0; mb < 4; mb++)                                     \
                _Pragma("unroll")                                              \
                for (int nb = 0; nb < 8; nb++)                                 \
                    mma_bf16(acc[mb][nb], afr[cur][mb],                        \
                             bfr[cur][nb >> 1][(nb & 1) * 2],                  \
                             bfr[cur][nb >> 1][(nb & 1) * 2 + 1]);             \
        }                                                                      \
    }

// epilogue for the tile whose labels/esq live at smem slot offset SLOT_OFF
#define EPILOGUE(iBaseV, SLOT_OFF)                                             \
    {                                                                          \
        float xs[4][2], es[8][2];                                              \
        int   lb[8][2];                                                        \
        _Pragma("unroll")                                                      \
        for (int mb = 0; mb < 4; mb++)                                         \
            _Pragma("unroll")                                                  \
            for (int h = 0; h < 2; h++)                                        \
                xs[mb][h] = g_xsq[(iBaseV) + wi * 64 + mb * 16 + gid + h * 8]; \
        _Pragma("unroll")                                                      \
        for (int nb = 0; nb < 8; nb++)                                         \
            _Pragma("unroll")                                                  \
            for (int w = 0; w < 2; w++) {                                      \
                int cl = wj * 64 + nb * 8 + tig * 2 + w;                       \
                es[nb][w] = esq_s[(SLOT_OFF) + cl];                            \
                lb[nb][w] = labs_s[(SLOT_OFF) + cl];                           \
            }                                                                  \
        _Pragma("unroll")                                                      \
        for (int mb = 0; mb < 4; mb++)                                         \
            _Pragma("unroll")                                                  \
            for (int nb = 0; nb < 8; nb++)                                     \
                _Pragma("unroll")                                              \
                for (int h = 0; h < 2; h++)                                    \
                    _Pragma("unroll")                                          \
                    for (int w = 0; w < 2; w++) {                              \
                        float d = xs[mb][h] + es[nb][w] - 2.f * acc[mb][nb][h * 2 + w]; \
                        acc[mb][nb][h * 2 + w] = __expf(-beta * d);            \
                    }                                                          \
        float cls0[4][4], cls1[4][4];                                          \
        _Pragma("unroll")                                                      \
        for (int mb = 0; mb < 4; mb++)                                         \
            _Pragma("unroll")                                                  \
            for (int q = 0; q < 4; q++) { cls0[mb][q] = 0.f; cls1[mb][q] = 0.f; } \
        _Pragma("unroll")                                                      \
        for (int nbp = 0; nbp < 4; nbp++) {                                    \
            const int n0 = 2 * nbp, n1 = 2 * nbp + 1;                          \
            uint32_t b0lo = onehot2(lb[n0][0], lb[n0][1], gid);                \
            uint32_t b1lo = onehot2(lb[n1][0], lb[n1][1], gid);                \
            uint32_t b0hi = onehot2(lb[n0][0], lb[n0][1], gid + 8);            \
            uint32_t b1hi = onehot2(lb[n1][0], lb[n1][1], gid + 8);            \
            _Pragma("unroll")                                                  \
            for (int mb = 0; mb < 4; mb++) {                                   \
                uint32_t af[4];                                                \
                af[0] = pack_bf16(acc[mb][n0][0], acc[mb][n0][1]);             \
                af[1] = pack_bf16(acc[mb][n0][2], acc[mb][n0][3]);             \
                af[2] = pack_bf16(acc[mb][n1][0], acc[mb][n1][1]);             \
                af[3] = pack_bf16(acc[mb][n1][2], acc[mb][n1][3]);             \
                mma_bf16(cls0[mb], af, b0lo, b1lo);                            \
                mma_bf16(cls1[mb], af, b0hi, b1hi);                            \
            }                                                                  \
        }                                                                      \
        _Pragma("unroll")                                                      \
        for (int mb = 0; mb < 4; mb++) {                                       \
            int r0 = wi * 64 + mb * 16 + gid;                                  \
            atomicAdd(&logit_s[r0 * NCLS + 2 * tig],           cls0[mb][0]);   \
            atomicAdd(&logit_s[r0 * NCLS + 2 * tig + 1],       cls0[mb][1]);   \
            atomicAdd(&logit_s[(r0 + 8) * NCLS + 2 * tig],     cls0[mb][2]);   \
            atomicAdd(&logit_s[(r0 + 8) * NCLS + 2 * tig + 1], cls0[mb][3]);   \
            if (tig == 0) {                                                    \
                atomicAdd(&logit_s[r0 * NCLS + 8],       cls1[mb][0]);         \
                atomicAdd(&logit_s[r0 * NCLS + 9],       cls1[mb][1]);         \
                atomicAdd(&logit_s[(r0 + 8) * NCLS + 8], cls1[mb][2]);         \
                atomicAdd(&logit_s[(r0 + 8) * NCLS + 9], cls1[mb][3]);         \
            }                                                                  \
        }                                                                      \
        __syncthreads();                                                       \
        for (int idx = tid; idx < BI * NCLS; idx += NTHREADS) {                \
            float v = logit_s[idx];                                            \
            atomicAdd(&g_logits[((iBaseV) + idx / NCLS) * NCLS + (idx % NCLS)], v); \
            logit_s[idx] = 0.f;                                                \
        }                                                                      \
    }

    // prologue: first two chunks of first tile
    STAGE_LOADS(bid, 0, 0); cp_commit();
    STAGE_LOADS(bid, 1, 1); cp_commit();

    float acc[4][8][4];
#pragma unroll
    for (int mb = 0; mb < 4; mb++)
#pragma unroll
        for (int nb = 0; nb < 8; nb++)
#pragma unroll
            for (int q = 0; q < 4; q++) acc[mb][nb][q] = 0.f;

    uint32_t afr[2][4][4], bfr[2][4][4];

    // ---------------- main loop: exactly 10 full tiles per CTA ----------------
    const int gEnd = 10 * NCHUNK;   // 80
    for (int g = 0; g < gEnd; g++) {
        const int kt   = g & 7;
        const int tIdx = g >> 3;
        const int tile = bid + tIdx * NCTAS;
        const int slot = tIdx & 1;

        if (kt == 0) {   // labels/esq for this tile (slot alternates; used at kt==7)
            int j = (tile >> 3) * BJ + tid;
            labs_s[slot * 128 + tid] = (j < J_DIM) ? labels[j] : 255;
            esq_s[slot * 128 + tid]  = g_esq[j];
        }

        cp_wait<STAGES - 2>();
        __syncthreads();   // chunk g visible; buf (g-1)%3 free

        int g2 = g + 2;
        if (g2 < gEnd) {
            int t2 = bid + (g2 >> 3) * NCTAS;
            STAGE_LOADS(t2, g2 & 7, g2 % 3);
        }
        cp_commit();   // always commit to keep wait_group accounting exact

        COMPUTE_CHUNK(g % 3);

        if (kt == 7) {
            const int iBase = (tile & 7) * BI;
            EPILOGUE(iBase, slot * 128);
#pragma unroll
            for (int mb = 0; mb < 4; mb++)
#pragma unroll
                for (int nb = 0; nb < 8; nb++)
#pragma unroll
                    for (int q = 0; q < 4; q++) acc[mb][nb][q] = 0.f;
        }
    }

    // ---------------- remainder: 88 tiles K-split across CTA pairs ----------------
    if (bid < 2 * NREM) {
        const int  c    = (bid < NREM) ? bid : (bid - NREM);
        const bool prod = (bid >= NREM);
        const int  tile = TFULL + c;
        const int  kt0  = prod ? 4 : 0;

        if (!prod) {   // consumer needs labels/esq for the epilogue (slot 0)
            int j = (tile >> 3) * BJ + tid;
            labs_s[tid] = (j < J_DIM) ? labels[j] : 255;
            esq_s[tid]  = g_esq[j];
        }

        STAGE_LOADS(tile, kt0 + 0, 0); cp_commit();
        STAGE_LOADS(tile, kt0 + 1, 1); cp_commit();

        for (int kt = 0; kt < 4; kt++) {
            cp_wait<STAGES - 2>();
            __syncthreads();
            if (kt < 2) STAGE_LOADS(tile, kt0 + kt + 2, (kt + 2) % 3);
            cp_commit();
            COMPUTE_CHUNK(kt % 3);
        }

        float* part = g_part + (size_t)c * (BI * BJ) + tid * 128;
        if (prod) {
            int idx = 0;
#pragma unroll
            for (int mb = 0; mb < 4; mb++)
#pragma unroll
                for (int nb = 0; nb < 8; nb++)
#pragma unroll
                    for (int q = 0; q < 4; q++) part[idx++] = acc[mb][nb][q];
            __threadfence();
            __syncthreads();
            if (tid == 0) atomicExch(&g_pflag[c], 1);
        } else {
            if (tid == 0) { while (atomicAdd(&g_pflag[c], 0) == 0) {} }
            __syncthreads();
            __threadfence();
            int idx = 0;
#pragma unroll
            for (int mb = 0; mb < 4; mb++)
#pragma unroll
                for (int nb = 0; nb < 8; nb++)
#pragma unroll
                    for (int q = 0; q < 4; q++) acc[mb][nb][q] += part[idx++];
            const int iBase = (tile & 7) * BI;
            EPILOGUE(iBase, 0);
        }
    }
#undef STAGE_LOADS
#undef COMPUTE_CHUNK
#undef EPILOGUE
}

// ---------------- softmax over [I_DIM, 10]; re-zeroes logits for next launch ----------------
__global__ void softmax_k(float* __restrict__ out, const float* __restrict__ gamma_p) {
    int row = blockIdx.x * blockDim.x + threadIdx.x;
    if (row >= I_DIM) return;
    float g = gamma_p[0];
    float v[NCLS];
    float m = -3.402823466e38f;
#pragma unroll
    for (int c = 0; c < NCLS; c++) {
        v[c] = g * g_logits[row * NCLS + c];
        m = fmaxf(m, v[c]);
    }
    float s = 0.f;
#pragma unroll
    for (int c = 0; c < NCLS; c++) { v[c] = __expf(v[c] - m); s += v[c]; }
    float inv = 1.f / s;
#pragma unroll
    for (int c = 0; c < NCLS; c++) {
        out[row * NCLS + c] = v[c] * inv;
        g_logits[row * NCLS + c] = 0.f;   // zero at load + re-zero here => every launch sees zeros
    }
}

// ---------------- launch ----------------
extern "C" void kernel_launch(void* const* d_in, const int* in_sizes, int n_in,
                              void* d_out, int out_size) {
    const float* x      = (const float*)d_in[0];
    const float* ex     = (const float*)d_in[1];
    const int*   labels = (const int*)  d_in[2];
    const float* Sinv   = (const float*)d_in[3];
    const float* beta   = (const float*)d_in[4];
    const float* gamma  = (const float*)d_in[5];
    float* out = (float*)d_out;

    cudaFuncSetAttribute(gemm_fused, cudaFuncAttributeMaxDynamicSharedMemorySize, SM_TOTAL);

    prep_all<<<J_PAD / 8, 256>>>((const float4*)x, (const float4*)ex, (const float4*)Sinv);

    gemm_fused<<<NCTAS, NTHREADS, SM_TOTAL>>>(labels, beta);

    softmax_k<<<(I_DIM + 255) / 256, 256>>>(out, gamma);
}

// round 16
// speedup vs baseline: 1.2162x; 1.2162x over previous
#include <cuda_runtime.h>
#include <cuda_bf16.h>
#include <cstdint>

#define I_DIM 1024
#define J_DIM 50000
#define J_PAD 50048            // 391 * 128
#define D_DIM 512
#define NCLS  10
#define BI 128
#define BJ 128
#define NCHUNK 8               // K chunks of 64 bf16 (128B per row)
#define STAGES 3
#define NTHREADS 128
#define NTILES ((I_DIM / BI) * (J_PAD / BJ))   // 3128
#define NCTAS 304                              // 2/SM x 152; 304 % 8 == 0 -> per-CTA iBase constant

// ---- dynamic smem layout (bytes) ----
#define STAGE_BYTES 32768      // A 16KB + B 16KB
#define SM_LABS   (STAGES * STAGE_BYTES)        // 98304: 2 x 128 ints (double-buffered)
#define SM_ESQ    (SM_LABS + 1024)              // 2 x 128 floats
#define SM_LOGIT  (SM_ESQ + 1024)               // 128*10 floats (accumulated across tiles)
#define SM_TOTAL  (SM_LOGIT + 5120)             // 105472 (x2 CTAs <= 227KB)

// ---------------- device scratch ----------------
__device__ __align__(16) __nv_bfloat16 g_xb[I_DIM * D_DIM];   // x * Sigma_inv
__device__ __align__(16) __nv_bfloat16 g_eb[J_PAD * D_DIM];   // exemplars
__device__ float g_xsq[I_DIM];
__device__ float g_esq[J_PAD];
__device__ float g_logits[I_DIM * NCLS];   // zero at load; re-zeroed by softmax_k each call

// ---------------- helpers ----------------
__device__ __forceinline__ uint32_t smem_u32(const void* p) {
    uint32_t a;
    asm("{ .reg .u64 t; cvta.to.shared.u64 t, %1; cvt.u32.u64 %0, t; }" : "=r"(a) : "l"(p));
    return a;
}
__device__ __forceinline__ void cp16(uint32_t dst, const void* src) {
    asm volatile("cp.async.cg.shared.global [%0], [%1], 16;" :: "r"(dst), "l"(src));
}
__device__ __forceinline__ void cp_commit() {
    asm volatile("cp.async.commit_group;" ::: "memory");
}
template <int N>
__device__ __forceinline__ void cp_wait() {
    asm volatile("cp.async.wait_group %0;" :: "n"(N) : "memory");
}
__device__ __forceinline__ void ldsm_x4(uint32_t r[4], uint32_t addr) {
    asm volatile("ldmatrix.sync.aligned.m8n8.x4.shared.b16 {%0,%1,%2,%3}, [%4];"
                 : "=r"(r[0]), "=r"(r[1]), "=r"(r[2]), "=r"(r[3]) : "r"(addr));
}
__device__ __forceinline__ void mma_bf16(float c[4], const uint32_t a[4], uint32_t b0, uint32_t b1) {
    asm volatile(
        "mma.sync.aligned.m16n8k16.row.col.f32.bf16.bf16.f32 "
        "{%0,%1,%2,%3}, {%4,%5,%6,%7}, {%8,%9}, {%0,%1,%2,%3};\n"
        : "+f"(c[0]), "+f"(c[1]), "+f"(c[2]), "+f"(c[3])
        : "r"(a[0]), "r"(a[1]), "r"(a[2]), "r"(a[3]), "r"(b0), "r"(b1));
}
__device__ __forceinline__ uint32_t pack_bf16(float lo, float hi) {
    uint32_t r;
    asm("cvt.rn.satfinite.bf16x2.f32 %0, %1, %2;" : "=r"(r) : "f"(hi), "f"(lo));
    return r;
}
// packed bf16x2 one-hot: {a==c, b==c}
__device__ __forceinline__ uint32_t onehot2(int a, int b, int c) {
    return ((a == c) ? 0x3F80u : 0u) | (((b == c) ? 0x3F80u : 0u) << 16);
}

// ---------------- prep: x & E convert + row norms (one kernel) ----------------
__global__ void prep_all(const float4* __restrict__ x4, const float4* __restrict__ e4,
                         const float4* __restrict__ S4) {
    const int blk  = blockIdx.x;
    const int wid  = threadIdx.x >> 5;
    const int lane = threadIdx.x & 31;

    // ---- E part (all blocks) ----
    {
        int row = blk * 8 + wid;
        uint2* dst = ((uint2*)g_eb) + (size_t)row * 128;
        if (row >= J_DIM) {
            uint2 z = {0u, 0u};
#pragma unroll
            for (int i = 0; i < 4; i++) dst[i * 32 + lane] = z;
            if (lane == 0) g_esq[row] = 0.f;
        } else {
            float sq = 0.f;
#pragma unroll
            for (int i = 0; i < 4; i++) {
                int idx = i * 32 + lane;
                float4 v = e4[(size_t)row * 128 + idx];
                float4 s = S4[idx];
                sq += v.x * v.x * s.x + v.y * v.y * s.y + v.z * v.z * s.z + v.w * v.w * s.w;
                uint2 o; o.x = pack_bf16(v.x, v.y); o.y = pack_bf16(v.z, v.w);
                dst[idx] = o;
            }
#pragma unroll
            for (int o = 16; o; o >>= 1) sq += __shfl_xor_sync(0xffffffffu, sq, o);
            if (lane == 0) g_esq[row] = sq;
        }
    }

    // ---- x part (blocks 0..127) ----
    if (blk < I_DIM / 8) {
        int row = blk * 8 + wid;
        float sq = 0.f;
        uint2* dst = ((uint2*)g_xb) + (size_t)row * 128;
#pragma unroll
        for (int i = 0; i < 4; i++) {
            int idx = i * 32 + lane;
            float4 v = x4[(size_t)row * 128 + idx];
            float4 s = S4[idx];
            float a0 = v.x * s.x, a1 = v.y * s.y, a2 = v.z * s.z, a3 = v.w * s.w;
            sq += v.x * a0 + v.y * a1 + v.z * a2 + v.w * a3;
            uint2 o; o.x = pack_bf16(a0, a1); o.y = pack_bf16(a2, a3);
            dst[idx] = o;
        }
#pragma unroll
        for (int o = 16; o; o >>= 1) sq += __shfl_xor_sync(0xffffffffu, sq, o);
        if (lane == 0) g_xsq[row] = sq;
    }
}

// ---------------- persistent fused GEMM: deferred logit flush ----------------
__global__ __launch_bounds__(NTHREADS, 2)
void gemm_fused(const int* __restrict__ labels, const float* __restrict__ beta_p) {
    extern __shared__ char smem[];
    const uint32_t sbase = smem_u32(smem);
    const int tid  = threadIdx.x;
    const int warp = tid >> 5;
    const int lane = tid & 31;
    const int gid  = lane >> 2;    // 0..7
    const int tig  = lane & 3;     // 0..3
    const int bid  = blockIdx.x;
    const int wi = warp & 1;       // i-half (64 rows)
    const int wj = warp >> 1;      // j-half (64 cols)

    int*   labs_s  = (int*)(smem + SM_LABS);     // [2][128]
    float* esq_s   = (float*)(smem + SM_ESQ);    // [2][128]
    float* logit_s = (float*)(smem + SM_LOGIT);  // accumulated across ALL this CTA's tiles

#pragma unroll
    for (int i = tid; i < BI * NCLS; i += NTHREADS) logit_s[i] = 0.f;

    // per-lane ldmatrix geometry (loop-invariant)
    const int lr = lane & 7;
    const int aRowOff = lr + ((lane >> 3) & 1) * 8;
    const int aColSel = (lane >> 4) << 4;
    const int bRowOff = lr + (lane >> 4) * 8;
    const int bColSel = ((lane >> 3) & 1) << 4;
    const int swx = lr << 4;

    uint32_t axt[4], bxt[4];
#pragma unroll
    for (int ks = 0; ks < 4; ks++) {
        axt[ks] = (uint32_t)((ks * 32 + aColSel) ^ swx);
        bxt[ks] = (uint32_t)((ks * 32 + bColSel) ^ swx);
    }
    const uint32_t aWarp = (uint32_t)((wi * 64 + aRowOff) * 128);
    const uint32_t bWarp = (uint32_t)((wj * 64 + bRowOff) * 128) + 16384;  // B after A (16KB)

    const float beta = beta_p[0];

    const int ntiles = (NTILES - bid + NCTAS - 1) / NCTAS;
    if (ntiles <= 0) return;
    const int gEnd = ntiles * NCHUNK;

    // NCTAS % 8 == 0  =>  (tile & 7) == (bid & 7) for every tile of this CTA
    const int iBase = (bid & 7) * BI;

    // tile t -> iBase = (t&7)*128 (constant per CTA), jBase = (t>>3)*128
#define STAGE_LOADS(t, chunk, buf)                                           \
    {                                                                        \
        const char* gA_ = (const char*)g_xb + (size_t)(((t) & 7) * BI) * 1024;   \
        const char* gB_ = (const char*)g_eb + (size_t)(((t) >> 3) * BJ) * 1024;  \
        const uint32_t dA = sbase + (buf) * STAGE_BYTES;                     \
        const uint32_t dB = dA + 16384;                                      \
        _Pragma("unroll")                                                    \
        for (int it = 0; it < 8; it++) {                                     \
            int idx = tid + it * NTHREADS;                                   \
            int r = idx >> 3, q = idx & 7;                                   \
            int off = r * 128 + ((q * 16) ^ ((r & 7) << 4));                 \
            cp16(dA + off, gA_ + (size_t)r * 1024 + (chunk) * 128 + q * 16); \
            cp16(dB + off, gB_ + (size_t)r * 1024 + (chunk) * 128 + q * 16); \
        }                                                                    \
    }

    // prologue: first two chunks of first tile
    STAGE_LOADS(bid, 0, 0); cp_commit();
    STAGE_LOADS(bid, 1, 1); cp_commit();

    float acc[4][8][4];
#pragma unroll
    for (int mb = 0; mb < 4; mb++)
#pragma unroll
        for (int nb = 0; nb < 8; nb++)
#pragma unroll
            for (int q = 0; q < 4; q++) acc[mb][nb][q] = 0.f;

    // per-CTA x row norms are also tile-invariant: load once
    float xs[4][2];
#pragma unroll
    for (int mb = 0; mb < 4; mb++)
#pragma unroll
        for (int h = 0; h < 2; h++)
            xs[mb][h] = g_xsq[iBase + wi * 64 + mb * 16 + gid + h * 8];

    uint32_t afr[2][4][4], bfr[2][4][4];

    for (int g = 0; g < gEnd; g++) {
        const int kt   = g & 7;
        const int tIdx = g >> 3;
        const int tile = bid + tIdx * NCTAS;
        const int slot = tIdx & 1;

        if (kt == 0) {   // load labels/esq for this tile (slot alternates; used at kt==7)
            int j = (tile >> 3) * BJ + tid;
            labs_s[slot * 128 + tid] = (j < J_DIM) ? labels[j] : 255;
            esq_s[slot * 128 + tid]  = g_esq[j];
        }

        cp_wait<STAGES - 2>();
        __syncthreads();   // chunk g visible; buf (g-1)%3 free

        int g2 = g + 2;
        if (g2 < gEnd) {
            int t2 = bid + (g2 >> 3) * NCTAS;
            STAGE_LOADS(t2, g2 & 7, g2 % 3);
        }
        cp_commit();   // always commit to keep wait_group accounting exact

        const uint32_t aCB = sbase + (g % 3) * STAGE_BYTES + aWarp;
        const uint32_t bCB = sbase + (g % 3) * STAGE_BYTES + bWarp;

#pragma unroll
        for (int mb = 0; mb < 4; mb++) ldsm_x4(afr[0][mb], aCB + mb * 2048 + axt[0]);
#pragma unroll
        for (int p = 0; p < 4; p++)  ldsm_x4(bfr[0][p],  bCB + p * 2048 + bxt[0]);

#pragma unroll
        for (int ks = 0; ks < 4; ks++) {
            const int cur = ks & 1;
            if (ks < 3) {
#pragma unroll
                for (int mb = 0; mb < 4; mb++)
                    ldsm_x4(afr[cur ^ 1][mb], aCB + mb * 2048 + axt[ks + 1]);
#pragma unroll
                for (int p = 0; p < 4; p++)
                    ldsm_x4(bfr[cur ^ 1][p], bCB + p * 2048 + bxt[ks + 1]);
            }
#pragma unroll
            for (int mb = 0; mb < 4; mb++)
#pragma unroll
                for (int nb = 0; nb < 8; nb++)
                    mma_bf16(acc[mb][nb], afr[cur][mb],
                             bfr[cur][nb >> 1][(nb & 1) * 2],
                             bfr[cur][nb >> 1][(nb & 1) * 2 + 1]);
        }

        if (kt == 7) {
            // ---------------- per-tile epilogue (accumulate into smem; no global flush) ----------------
            float es[8][2];
            int   lb[8][2];
#pragma unroll
            for (int nb = 0; nb < 8; nb++)
#pragma unroll
                for (int w = 0; w < 2; w++) {
                    int cl = wj * 64 + nb * 8 + tig * 2 + w;
                    es[nb][w] = esq_s[slot * 128 + cl];
                    lb[nb][w] = labs_s[slot * 128 + cl];
                }

#pragma unroll
            for (int mb = 0; mb < 4; mb++)
#pragma unroll
                for (int nb = 0; nb < 8; nb++)
#pragma unroll
                    for (int h = 0; h < 2; h++)
#pragma unroll
                        for (int w = 0; w < 2; w++) {
                            float d = xs[mb][h] + es[nb][w] - 2.f * acc[mb][nb][h * 2 + w];
                            acc[mb][nb][h * 2 + w] = __expf(-beta * d);
                        }

            float cls0[4][4], cls1[4][4];
#pragma unroll
            for (int mb = 0; mb < 4; mb++)
#pragma unroll
                for (int q = 0; q < 4; q++) { cls0[mb][q] = 0.f; cls1[mb][q] = 0.f; }

#pragma unroll
            for (int nbp = 0; nbp < 4; nbp++) {
                const int n0 = 2 * nbp, n1 = 2 * nbp + 1;
                uint32_t b0lo = onehot2(lb[n0][0], lb[n0][1], gid);
                uint32_t b1lo = onehot2(lb[n1][0], lb[n1][1], gid);
                uint32_t b0hi = onehot2(lb[n0][0], lb[n0][1], gid + 8);
                uint32_t b1hi = onehot2(lb[n1][0], lb[n1][1], gid + 8);
#pragma unroll
                for (int mb = 0; mb < 4; mb++) {
                    uint32_t af[4];
                    af[0] = pack_bf16(acc[mb][n0][0], acc[mb][n0][1]);
                    af[1] = pack_bf16(acc[mb][n0][2], acc[mb][n0][3]);
                    af[2] = pack_bf16(acc[mb][n1][0], acc[mb][n1][1]);
                    af[3] = pack_bf16(acc[mb][n1][2], acc[mb][n1][3]);
                    mma_bf16(cls0[mb], af, b0lo, b1lo);   // classes 0..7
                    mma_bf16(cls1[mb], af, b0hi, b1hi);   // classes 8,9
                }
            }

#pragma unroll
            for (int mb = 0; mb < 4; mb++) {
                int r0 = wi * 64 + mb * 16 + gid;
                atomicAdd(&logit_s[r0 * NCLS + 2 * tig],           cls0[mb][0]);
                atomicAdd(&logit_s[r0 * NCLS + 2 * tig + 1],       cls0[mb][1]);
                atomicAdd(&logit_s[(r0 + 8) * NCLS + 2 * tig],     cls0[mb][2]);
                atomicAdd(&logit_s[(r0 + 8) * NCLS + 2 * tig + 1], cls0[mb][3]);
                if (tig == 0) {
                    atomicAdd(&logit_s[r0 * NCLS + 8],       cls1[mb][0]);
                    atomicAdd(&logit_s[r0 * NCLS + 9],       cls1[mb][1]);
                    atomicAdd(&logit_s[(r0 + 8) * NCLS + 8], cls1[mb][2]);
                    atomicAdd(&logit_s[(r0 + 8) * NCLS + 9], cls1[mb][3]);
                }
            }

            // reset acc for next tile (no barrier/flush here)
#pragma unroll
            for (int mb = 0; mb < 4; mb++)
#pragma unroll
                for (int nb = 0; nb < 8; nb++)
#pragma unroll
                    for (int q = 0; q < 4; q++) acc[mb][nb][q] = 0.f;
        }
    }

    // ---------------- single deferred flush (same 128 rows for all this CTA's tiles) ----------------
    __syncthreads();
    for (int idx = tid; idx < BI * NCLS; idx += NTHREADS) {
        atomicAdd(&g_logits[(iBase + idx / NCLS) * NCLS + (idx % NCLS)], logit_s[idx]);
    }
#undef STAGE_LOADS
}

// ---------------- softmax over [I_DIM, 10]; re-zeroes logits for next launch ----------------
__global__ void softmax_k(float* __restrict__ out, const float* __restrict__ gamma_p) {
    int row = blockIdx.x * blockDim.x + threadIdx.x;
    if (row >= I_DIM) return;
    float g = gamma_p[0];
    float v[NCLS];
    float m = -3.402823466e38f;
#pragma unroll
    for (int c = 0; c < NCLS; c++) {
        v[c] = g * g_logits[row * NCLS + c];
        m = fmaxf(m, v[c]);
    }
    float s = 0.f;
#pragma unroll
    for (int c = 0; c < NCLS; c++) { v[c] = __expf(v[c] - m); s += v[c]; }
    float inv = 1.f / s;
#pragma unroll
    for (int c = 0; c < NCLS; c++) {
        out[row * NCLS + c] = v[c] * inv;
        g_logits[row * NCLS + c] = 0.f;   // zero at load + re-zero here => every launch sees zeros
    }
}

// ---------------- launch ----------------
extern "C" void kernel_launch(void* const* d_in, const int* in_sizes, int n_in,
                              void* d_out, int out_size) {
    const float* x      = (const float*)d_in[0];
    const float* ex     = (const float*)d_in[1];
    const int*   labels = (const int*)  d_in[2];
    const float* Sinv   = (const float*)d_in[3];
    const float* beta   = (const float*)d_in[4];
    const float* gamma  = (const float*)d_in[5];
    float* out = (float*)d_out;

    cudaFuncSetAttribute(gemm_fused, cudaFuncAttributeMaxDynamicSharedMemorySize, SM_TOTAL);

    prep_all<<<J_PAD / 8, 256>>>((const float4*)x, (const float4*)ex, (const float4*)Sinv);

    gemm_fused<<<NCTAS, NTHREADS, SM_TOTAL>>>(labels, beta);

    softmax_k<<<(I_DIM + 255) / 256, 256>>>(out, gamma);
}

// round 17
// speedup vs baseline: 1.2463x; 1.0247x over previous
#include <cuda_runtime.h>
#include <cuda_bf16.h>
#include <cstdint>

#define I_DIM 1024
#define J_DIM 50000
#define J_PAD 50048            // 391 * 128
#define D_DIM 512
#define NCLS  10
#define BI 128
#define BJ 128
#define NCHUNK 8               // K chunks of 64 bf16 (128B per row)
#define STAGES 3
#define NTHREADS 128
#define NTILES ((I_DIM / BI) * (J_PAD / BJ))   // 3128
#define NCTAS 304                              // 2/SM x 152; 304 % 8 == 0 -> per-CTA iBase constant

// ---- dynamic smem layout (bytes) ----
#define STAGE_BYTES 32768      // A 16KB + B 16KB
#define SM_LABS   (STAGES * STAGE_BYTES)        // 98304: 2 x 128 ints (double-buffered)
#define SM_ESQ    (SM_LABS + 1024)              // 2 x 128 floats
#define SM_TOTAL  (SM_ESQ + 1024)               // 100352 (x2 CTAs <= 227KB)

// ---------------- device scratch ----------------
__device__ __align__(16) __nv_bfloat16 g_xb[I_DIM * D_DIM];   // x * Sigma_inv
__device__ __align__(16) __nv_bfloat16 g_eb[J_PAD * D_DIM];   // exemplars
__device__ float g_xsq[I_DIM];
__device__ float g_esq[J_PAD];
__device__ float g_logits[I_DIM * NCLS];   // zero at load; re-zeroed by softmax_k each call

// ---------------- helpers ----------------
__device__ __forceinline__ uint32_t smem_u32(const void* p) {
    uint32_t a;
    asm("{ .reg .u64 t; cvta.to.shared.u64 t, %1; cvt.u32.u64 %0, t; }" : "=r"(a) : "l"(p));
    return a;
}
__device__ __forceinline__ void cp16(uint32_t dst, const void* src) {
    asm volatile("cp.async.cg.shared.global [%0], [%1], 16;" :: "r"(dst), "l"(src));
}
__device__ __forceinline__ void cp_commit() {
    asm volatile("cp.async.commit_group;" ::: "memory");
}
template <int N>
__device__ __forceinline__ void cp_wait() {
    asm volatile("cp.async.wait_group %0;" :: "n"(N) : "memory");
}
__device__ __forceinline__ void ldsm_x4(uint32_t r[4], uint32_t addr) {
    asm volatile("ldmatrix.sync.aligned.m8n8.x4.shared.b16 {%0,%1,%2,%3}, [%4];"
                 : "=r"(r[0]), "=r"(r[1]), "=r"(r[2]), "=r"(r[3]) : "r"(addr));
}
__device__ __forceinline__ void mma_bf16(float c[4], const uint32_t a[4], uint32_t b0, uint32_t b1) {
    asm volatile(
        "mma.sync.aligned.m16n8k16.row.col.f32.bf16.bf16.f32 "
        "{%0,%1,%2,%3}, {%4,%5,%6,%7}, {%8,%9}, {%0,%1,%2,%3};\n"
        : "+f"(c[0]), "+f"(c[1]), "+f"(c[2]), "+f"(c[3])
        : "r"(a[0]), "r"(a[1]), "r"(a[2]), "r"(a[3]), "r"(b0), "r"(b1));
}
__device__ __forceinline__ uint32_t pack_bf16(float lo, float hi) {
    uint32_t r;
    asm("cvt.rn.satfinite.bf16x2.f32 %0, %1, %2;" : "=r"(r) : "f"(hi), "f"(lo));
    return r;
}
// packed bf16x2 one-hot: {a==c, b==c}
__device__ __forceinline__ uint32_t onehot2(int a, int b, int c) {
    return ((a == c) ? 0x3F80u : 0u) | (((b == c) ? 0x3F80u : 0u) << 16);
}

// ---------------- prep: x & E convert + row norms (one kernel) ----------------
__global__ void prep_all(const float4* __restrict__ x4, const float4* __restrict__ e4,
                         const float4* __restrict__ S4) {
    const int blk  = blockIdx.x;
    const int wid  = threadIdx.x >> 5;
    const int lane = threadIdx.x & 31;

    // ---- E part (all blocks) ----
    {
        int row = blk * 8 + wid;
        uint2* dst = ((uint2*)g_eb) + (size_t)row * 128;
        if (row >= J_DIM) {
            uint2 z = {0u, 0u};
#pragma unroll
            for (int i = 0; i < 4; i++) dst[i * 32 + lane] = z;
            if (lane == 0) g_esq[row] = 0.f;
        } else {
            float sq = 0.f;
#pragma unroll
            for (int i = 0; i < 4; i++) {
                int idx = i * 32 + lane;
                float4 v = e4[(size_t)row * 128 + idx];
                float4 s = S4[idx];
                sq += v.x * v.x * s.x + v.y * v.y * s.y + v.z * v.z * s.z + v.w * v.w * s.w;
                uint2 o; o.x = pack_bf16(v.x, v.y); o.y = pack_bf16(v.z, v.w);
                dst[idx] = o;
            }
#pragma unroll
            for (int o = 16; o; o >>= 1) sq += __shfl_xor_sync(0xffffffffu, sq, o);
            if (lane == 0) g_esq[row] = sq;
        }
    }

    // ---- x part (blocks 0..127) ----
    if (blk < I_DIM / 8) {
        int row = blk * 8 + wid;
        float sq = 0.f;
        uint2* dst = ((uint2*)g_xb) + (size_t)row * 128;
#pragma unroll
        for (int i = 0; i < 4; i++) {
            int idx = i * 32 + lane;
            float4 v = x4[(size_t)row * 128 + idx];
            float4 s = S4[idx];
            float a0 = v.x * s.x, a1 = v.y * s.y, a2 = v.z * s.z, a3 = v.w * s.w;
            sq += v.x * a0 + v.y * a1 + v.z * a2 + v.w * a3;
            uint2 o; o.x = pack_bf16(a0, a1); o.y = pack_bf16(a2, a3);
            dst[idx] = o;
        }
#pragma unroll
        for (int o = 16; o; o >>= 1) sq += __shfl_xor_sync(0xffffffffu, sq, o);
        if (lane == 0) g_xsq[row] = sq;
    }
}

// ---------------- persistent fused GEMM: cls accumulated in registers across tiles ----------------
__global__ __launch_bounds__(NTHREADS, 2)
void gemm_fused(const int* __restrict__ labels, const float* __restrict__ beta_p) {
    extern __shared__ char smem[];
    const uint32_t sbase = smem_u32(smem);
    const int tid  = threadIdx.x;
    const int warp = tid >> 5;
    const int lane = tid & 31;
    const int gid  = lane >> 2;    // 0..7
    const int tig  = lane & 3;     // 0..3
    const int bid  = blockIdx.x;
    const int wi = warp & 1;       // i-half (64 rows)
    const int wj = warp >> 1;      // j-half (64 cols)

    int*   labs_s  = (int*)(smem + SM_LABS);     // [2][128]
    float* esq_s   = (float*)(smem + SM_ESQ);    // [2][128]

    // per-lane ldmatrix geometry (loop-invariant)
    const int lr = lane & 7;
    const int aRowOff = lr + ((lane >> 3) & 1) * 8;
    const int aColSel = (lane >> 4) << 4;
    const int bRowOff = lr + (lane >> 4) * 8;
    const int bColSel = ((lane >> 3) & 1) << 4;
    const int swx = lr << 4;

    uint32_t axt[4], bxt[4];
#pragma unroll
    for (int ks = 0; ks < 4; ks++) {
        axt[ks] = (uint32_t)((ks * 32 + aColSel) ^ swx);
        bxt[ks] = (uint32_t)((ks * 32 + bColSel) ^ swx);
    }
    const uint32_t aWarp = (uint32_t)((wi * 64 + aRowOff) * 128);
    const uint32_t bWarp = (uint32_t)((wj * 64 + bRowOff) * 128) + 16384;  // B after A (16KB)

    const float beta = beta_p[0];

    const int ntiles = (NTILES - bid + NCTAS - 1) / NCTAS;
    if (ntiles <= 0) return;
    const int gEnd = ntiles * NCHUNK;

    // NCTAS % 8 == 0  =>  (tile & 7) == (bid & 7) for every tile of this CTA
    const int iBase = (bid & 7) * BI;

    // tile t -> iBase = (t&7)*128 (constant per CTA), jBase = (t>>3)*128
#define STAGE_LOADS(t, chunk, buf)                                           \
    {                                                                        \
        const char* gA_ = (const char*)g_xb + (size_t)(((t) & 7) * BI) * 1024;   \
        const char* gB_ = (const char*)g_eb + (size_t)(((t) >> 3) * BJ) * 1024;  \
        const uint32_t dA = sbase + (buf) * STAGE_BYTES;                     \
        const uint32_t dB = dA + 16384;                                      \
        _Pragma("unroll")                                                    \
        for (int it = 0; it < 8; it++) {                                     \
            int idx = tid + it * NTHREADS;                                   \
            int r = idx >> 3, q = idx & 7;                                   \
            int off = r * 128 + ((q * 16) ^ ((r & 7) << 4));                 \
            cp16(dA + off, gA_ + (size_t)r * 1024 + (chunk) * 128 + q * 16); \
            cp16(dB + off, gB_ + (size_t)r * 1024 + (chunk) * 128 + q * 16); \
        }                                                                    \
    }

    // prologue: first two chunks of first tile
    STAGE_LOADS(bid, 0, 0); cp_commit();
    STAGE_LOADS(bid, 1, 1); cp_commit();

    float acc[4][8][4];
#pragma unroll
    for (int mb = 0; mb < 4; mb++)
#pragma unroll
        for (int nb = 0; nb < 8; nb++)
#pragma unroll
            for (int q = 0; q < 4; q++) acc[mb][nb][q] = 0.f;

    // per-CTA x row norms are tile-invariant: load once
    float xs[4][2];
#pragma unroll
    for (int mb = 0; mb < 4; mb++)
#pragma unroll
        for (int h = 0; h < 2; h++)
            xs[mb][h] = g_xsq[iBase + wi * 64 + mb * 16 + gid + h * 8];

    // class sums accumulated in registers across ALL this CTA's tiles
    float cls0[4][4], cls1[4][4];
#pragma unroll
    for (int mb = 0; mb < 4; mb++)
#pragma unroll
        for (int q = 0; q < 4; q++) { cls0[mb][q] = 0.f; cls1[mb][q] = 0.f; }

    uint32_t afr[2][4][4], bfr[2][4][4];

    for (int g = 0; g < gEnd; g++) {
        const int kt   = g & 7;
        const int tIdx = g >> 3;
        const int tile = bid + tIdx * NCTAS;
        const int slot = tIdx & 1;

        if (kt == 0) {   // load labels/esq for this tile (slot alternates; used at kt==7)
            int j = (tile >> 3) * BJ + tid;
            labs_s[slot * 128 + tid] = (j < J_DIM) ? labels[j] : 255;
            esq_s[slot * 128 + tid]  = g_esq[j];
        }

        cp_wait<STAGES - 2>();
        __syncthreads();   // chunk g visible; buf (g-1)%3 free

        int g2 = g + 2;
        if (g2 < gEnd) {
            int t2 = bid + (g2 >> 3) * NCTAS;
            STAGE_LOADS(t2, g2 & 7, g2 % 3);
        }
        cp_commit();   // always commit to keep wait_group accounting exact

        const uint32_t aCB = sbase + (g % 3) * STAGE_BYTES + aWarp;
        const uint32_t bCB = sbase + (g % 3) * STAGE_BYTES + bWarp;

#pragma unroll
        for (int mb = 0; mb < 4; mb++) ldsm_x4(afr[0][mb], aCB + mb * 2048 + axt[0]);
#pragma unroll
        for (int p = 0; p < 4; p++)  ldsm_x4(bfr[0][p],  bCB + p * 2048 + bxt[0]);

#pragma unroll
        for (int ks = 0; ks < 4; ks++) {
            const int cur = ks & 1;
            if (ks < 3) {
#pragma unroll
                for (int mb = 0; mb < 4; mb++)
                    ldsm_x4(afr[cur ^ 1][mb], aCB + mb * 2048 + axt[ks + 1]);
#pragma unroll
                for (int p = 0; p < 4; p++)
                    ldsm_x4(bfr[cur ^ 1][p], bCB + p * 2048 + bxt[ks + 1]);
            }
#pragma unroll
            for (int mb = 0; mb < 4; mb++)
#pragma unroll
                for (int nb = 0; nb < 8; nb++)
                    mma_bf16(acc[mb][nb], afr[cur][mb],
                             bfr[cur][nb >> 1][(nb & 1) * 2],
                             bfr[cur][nb >> 1][(nb & 1) * 2 + 1]);
        }

        if (kt == 7) {
            // ------- per-tile epilogue: exp -> pack -> accumulate into cls via mma -------
            float es[8][2];
            int   lb[8][2];
#pragma unroll
            for (int nb = 0; nb < 8; nb++)
#pragma unroll
                for (int w = 0; w < 2; w++) {
                    int cl = wj * 64 + nb * 8 + tig * 2 + w;
                    es[nb][w] = esq_s[slot * 128 + cl];
                    lb[nb][w] = labs_s[slot * 128 + cl];
                }

#pragma unroll
            for (int mb = 0; mb < 4; mb++)
#pragma unroll
                for (int nb = 0; nb < 8; nb++)
#pragma unroll
                    for (int h = 0; h < 2; h++)
#pragma unroll
                        for (int w = 0; w < 2; w++) {
                            float d = xs[mb][h] + es[nb][w] - 2.f * acc[mb][nb][h * 2 + w];
                            acc[mb][nb][h * 2 + w] = __expf(-beta * d);
                        }

#pragma unroll
            for (int nbp = 0; nbp < 4; nbp++) {
                const int n0 = 2 * nbp, n1 = 2 * nbp + 1;
                uint32_t b0lo = onehot2(lb[n0][0], lb[n0][1], gid);
                uint32_t b1lo = onehot2(lb[n1][0], lb[n1][1], gid);
                uint32_t b0hi = onehot2(lb[n0][0], lb[n0][1], gid + 8);
                uint32_t b1hi = onehot2(lb[n1][0], lb[n1][1], gid + 8);
#pragma unroll
                for (int mb = 0; mb < 4; mb++) {
                    uint32_t af[4];
                    af[0] = pack_bf16(acc[mb][n0][0], acc[mb][n0][1]);
                    af[1] = pack_bf16(acc[mb][n0][2], acc[mb][n0][3]);
                    af[2] = pack_bf16(acc[mb][n1][0], acc[mb][n1][1]);
                    af[3] = pack_bf16(acc[mb][n1][2], acc[mb][n1][3]);
                    mma_bf16(cls0[mb], af, b0lo, b1lo);   // classes 0..7 (accumulates across tiles)
                    mma_bf16(cls1[mb], af, b0hi, b1hi);   // classes 8,9
                }
            }

            // reset acc for next tile (cls persists)
#pragma unroll
            for (int mb = 0; mb < 4; mb++)
#pragma unroll
                for (int nb = 0; nb < 8; nb++)
#pragma unroll
                    for (int q = 0; q < 4; q++) acc[mb][nb][q] = 0.f;
        }
    }

    // ---------------- single deferred flush: direct global atomics ----------------
#pragma unroll
    for (int mb = 0; mb < 4; mb++) {
        int r0 = iBase + wi * 64 + mb * 16 + gid;
        atomicAdd(&g_logits[r0 * NCLS + 2 * tig],             cls0[mb][0]);
        atomicAdd(&g_logits[r0 * NCLS + 2 * tig + 1],         cls0[mb][1]);
        atomicAdd(&g_logits[(r0 + 8) * NCLS + 2 * tig],       cls0[mb][2]);
        atomicAdd(&g_logits[(r0 + 8) * NCLS + 2 * tig + 1],   cls0[mb][3]);
        if (tig == 0) {
            atomicAdd(&g_logits[r0 * NCLS + 8],       cls1[mb][0]);
            atomicAdd(&g_logits[r0 * NCLS + 9],       cls1[mb][1]);
            atomicAdd(&g_logits[(r0 + 8) * NCLS + 8], cls1[mb][2]);
            atomicAdd(&g_logits[(r0 + 8) * NCLS + 9], cls1[mb][3]);
        }
    }
#undef STAGE_LOADS
}

// ---------------- softmax over [I_DIM, 10]; re-zeroes logits for next launch ----------------
__global__ void softmax_k(float* __restrict__ out, const float* __restrict__ gamma_p) {
    int row = blockIdx.x * blockDim.x + threadIdx.x;
    if (row >= I_DIM) return;
    float g = gamma_p[0];
    float v[NCLS];
    float m = -3.402823466e38f;
#pragma unroll
    for (int c = 0; c < NCLS; c++) {
        v[c] = g * g_logits[row * NCLS + c];
        m = fmaxf(m, v[c]);
    }
    float s = 0.f;
#pragma unroll
    for (int c = 0; c < NCLS; c++) { v[c] = __expf(v[c] - m); s += v[c]; }
    float inv = 1.f / s;
#pragma unroll
    for (int c = 0; c < NCLS; c++) {
        out[row * NCLS + c] = v[c] * inv;
        g_logits[row * NCLS + c] = 0.f;   // zero at load + re-zero here => every launch sees zeros
    }
}

// ---------------- launch ----------------
extern "C" void kernel_launch(void* const* d_in, const int* in_sizes, int n_in,
                              void* d_out, int out_size) {
    const float* x      = (const float*)d_in[0];
    const float* ex     = (const float*)d_in[1];
    const int*   labels = (const int*)  d_in[2];
    const float* Sinv   = (const float*)d_in[3];
    const float* beta   = (const float*)d_in[4];
    const float* gamma  = (const float*)d_in[5];
    float* out = (float*)d_out;

    cudaFuncSetAttribute(gemm_fused, cudaFuncAttributeMaxDynamicSharedMemorySize, SM_TOTAL);

    prep_all<<<J_PAD / 8, 256>>>((const float4*)x, (const float4*)ex, (const float4*)Sinv);

    gemm_fused<<<NCTAS, NTHREADS, SM_TOTAL>>>(labels, beta);

    softmax_k<<<(I_DIM + 255) / 256, 256>>>(out, gamma);
}